// round 2
// baseline (speedup 1.0000x reference)
#include <cuda_runtime.h>
#include <cuda_bf16.h>
#include <math.h>

// Problem constants (fixed by the dataset)
#define BB   2
#define SQ   1024
#define DM   1024
#define NH   16
#define DK   64
#define DFF  2048
#define NL   4

// ---------------------------------------------------------------------------
// Scratch (device globals — no allocation allowed)
// ---------------------------------------------------------------------------
__device__ __align__(16) float g_q[BB * SQ * DM];
__device__ __align__(16) float g_k[BB * SQ * DM];
__device__ __align__(16) float g_v[BB * SQ * DM];
__device__ __align__(16) float g_x[BB * SQ * DM];
__device__ __align__(16) float g_t[BB * SQ * DM];
__device__ __align__(16) float g_h[BB * SQ * DFF];

// ---------------------------------------------------------------------------
// Helpers
// ---------------------------------------------------------------------------
__device__ __forceinline__ float gelu_tanh_f(float x) {
    float x3 = x * x * x;
    return 0.5f * x * (1.0f + tanhf(0.7978845608028654f * (x + 0.044715f * x3)));
}

__device__ __forceinline__ float block_sum256(float v, float* sh) {
    #pragma unroll
    for (int o = 16; o; o >>= 1) v += __shfl_xor_sync(0xffffffffu, v, o);
    int w = threadIdx.x >> 5;
    if ((threadIdx.x & 31) == 0) sh[w] = v;
    __syncthreads();
    float r = (threadIdx.x < 8) ? sh[threadIdx.x] : 0.0f;
    if (threadIdx.x < 32) {
        #pragma unroll
        for (int o = 4; o; o >>= 1) r += __shfl_xor_sync(0xffffffffu, r, o);
        if (threadIdx.x == 0) sh[0] = r;
    }
    __syncthreads();
    r = sh[0];
    __syncthreads();
    return r;
}

__device__ __forceinline__ float block_max256(float v, float* sh) {
    #pragma unroll
    for (int o = 16; o; o >>= 1) v = fmaxf(v, __shfl_xor_sync(0xffffffffu, v, o));
    int w = threadIdx.x >> 5;
    if ((threadIdx.x & 31) == 0) sh[w] = v;
    __syncthreads();
    float r = (threadIdx.x < 8) ? sh[threadIdx.x] : -3.4e38f;
    if (threadIdx.x < 32) {
        #pragma unroll
        for (int o = 4; o; o >>= 1) r = fmaxf(r, __shfl_xor_sync(0xffffffffu, r, o));
        if (threadIdx.x == 0) sh[0] = r;
    }
    __syncthreads();
    r = sh[0];
    __syncthreads();
    return r;
}

// ---------------------------------------------------------------------------
// Generic NN GEMM: C[M,N] = A[M,K] * B[K,N] (+bias)(+gelu)
// 64x64 block tile, BK=16, 256 threads, 4x4 per-thread micro-tile.
// EPI: 0 = none, 1 = +bias, 2 = +bias then gelu
// ATTN: if 1, blockIdx.z = b*NH + h; pointers offset for the PV batched gemm:
//   A += z*SQ*SQ ; B,C += b*SQ*DM + h*DK
// ---------------------------------------------------------------------------
template<int EPI, int ATTN>
__global__ void __launch_bounds__(256) gemm_nn(
    const float* __restrict__ A, const float* __restrict__ Bm,
    float* __restrict__ C, const float* __restrict__ bias,
    int M, int N, int K, int lda, int ldb, int ldc)
{
    if (ATTN) {
        int z = blockIdx.z;
        int b = z >> 4;      // NH = 16
        int h = z & 15;
        A  += (long)z * SQ * SQ;
        Bm += (long)b * SQ * DM + h * DK;
        C  += (long)b * SQ * DM + h * DK;
    }
    __shared__ __align__(16) float As[16][64];
    __shared__ __align__(16) float Bs[16][64];

    int t   = threadIdx.x;
    int tx  = t & 15;
    int ty  = t >> 4;
    int row0 = blockIdx.y * 64;
    int col0 = blockIdx.x * 64;

    int aM = t >> 2;            // 0..63
    int aK = (t & 3) * 4;       // 0,4,8,12
    int bK = t >> 4;            // 0..15
    int bN = (t & 15) * 4;      // 0..60

    float acc[4][4];
    #pragma unroll
    for (int i = 0; i < 4; i++)
        #pragma unroll
        for (int j = 0; j < 4; j++) acc[i][j] = 0.0f;

    for (int k0 = 0; k0 < K; k0 += 16) {
        float4 av = *(const float4*)&A[(long)(row0 + aM) * lda + k0 + aK];
        float4 bv = *(const float4*)&Bm[(long)(k0 + bK) * ldb + col0 + bN];
        As[aK + 0][aM] = av.x;
        As[aK + 1][aM] = av.y;
        As[aK + 2][aM] = av.z;
        As[aK + 3][aM] = av.w;
        *(float4*)&Bs[bK][bN] = bv;
        __syncthreads();

        #pragma unroll
        for (int kk = 0; kk < 16; kk++) {
            float4 a4 = *(const float4*)&As[kk][ty * 4];
            float4 b4 = *(const float4*)&Bs[kk][tx * 4];
            float ar[4] = {a4.x, a4.y, a4.z, a4.w};
            float br[4] = {b4.x, b4.y, b4.z, b4.w};
            #pragma unroll
            for (int i = 0; i < 4; i++)
                #pragma unroll
                for (int j = 0; j < 4; j++)
                    acc[i][j] += ar[i] * br[j];
        }
        __syncthreads();
    }

    #pragma unroll
    for (int i = 0; i < 4; i++) {
        long r = row0 + ty * 4 + i;
        float vv[4];
        #pragma unroll
        for (int j = 0; j < 4; j++) {
            float v = acc[i][j];
            if (EPI >= 1) v += bias[col0 + tx * 4 + j];
            if (EPI == 2) v = gelu_tanh_f(v);
            vv[j] = v;
        }
        *(float4*)&C[r * ldc + col0 + tx * 4] = make_float4(vv[0], vv[1], vv[2], vv[3]);
    }
}

// ---------------------------------------------------------------------------
// Attention scores: s[b,h,i,j] = (q[b,h,i,:] . k[b,h,j,:]) * scale + bias - mask
// q,k stored as [B,S,D] with head h at columns h*DK..h*DK+63.
// grid: (S/64, S/64, B*NH), 256 threads, 4x4 micro-tile, K=64 fully in smem.
// ---------------------------------------------------------------------------
__global__ void __launch_bounds__(256) attn_scores(
    const float* __restrict__ q, const float* __restrict__ k,
    const float* __restrict__ bias, const int* __restrict__ mask,
    float* __restrict__ p)
{
    __shared__ __align__(16) float Qs[64][64];
    __shared__ __align__(16) float Ks[64][64];

    int z = blockIdx.z;
    int b = z >> 4;
    int h = z & 15;
    const float* qb = q + (long)b * SQ * DM + h * DK;
    const float* kb = k + (long)b * SQ * DM + h * DK;
    int qi0 = blockIdx.y * 64;
    int kj0 = blockIdx.x * 64;
    int t = threadIdx.x;

    #pragma unroll
    for (int r = 0; r < 4; r++) {
        int lin = t * 16 + r * 4;
        int m  = lin >> 6;
        int dd = lin & 63;
        float4 qv = *(const float4*)&qb[(long)(qi0 + m) * DM + dd];
        float4 kv = *(const float4*)&kb[(long)(kj0 + m) * DM + dd];
        Qs[dd + 0][m] = qv.x; Qs[dd + 1][m] = qv.y; Qs[dd + 2][m] = qv.z; Qs[dd + 3][m] = qv.w;
        Ks[dd + 0][m] = kv.x; Ks[dd + 1][m] = kv.y; Ks[dd + 2][m] = kv.z; Ks[dd + 3][m] = kv.w;
    }
    __syncthreads();

    int tx = t & 15;
    int ty = t >> 4;
    float acc[4][4];
    #pragma unroll
    for (int i = 0; i < 4; i++)
        #pragma unroll
        for (int j = 0; j < 4; j++) acc[i][j] = 0.0f;

    #pragma unroll
    for (int d = 0; d < 64; d++) {
        float4 a4 = *(const float4*)&Qs[d][ty * 4];
        float4 b4 = *(const float4*)&Ks[d][tx * 4];
        float ar[4] = {a4.x, a4.y, a4.z, a4.w};
        float br[4] = {b4.x, b4.y, b4.z, b4.w};
        #pragma unroll
        for (int i = 0; i < 4; i++)
            #pragma unroll
            for (int j = 0; j < 4; j++)
                acc[i][j] += ar[i] * br[j];
    }

    const float scale = 0.125f;  // 1/sqrt(64)
    int4 mk = *(const int4*)&mask[b * SQ + kj0 + tx * 4];
    int mks[4] = {mk.x, mk.y, mk.z, mk.w};

    #pragma unroll
    for (int i = 0; i < 4; i++) {
        long qi = qi0 + ty * 4 + i;
        const float* brow = bias + ((long)z * SQ + qi) * SQ + kj0;
        float* prow = p + ((long)z * SQ + qi) * SQ + kj0;
        float4 bi = *(const float4*)&brow[tx * 4];
        float bb[4] = {bi.x, bi.y, bi.z, bi.w};
        float vv[4];
        #pragma unroll
        for (int j = 0; j < 4; j++) {
            float v = acc[i][j] * scale + bb[j];
            if (mks[j] == 0) v = -9e15f;
            vv[j] = v;
        }
        *(float4*)&prow[tx * 4] = make_float4(vv[0], vv[1], vv[2], vv[3]);
    }
}

// ---------------------------------------------------------------------------
// Row softmax in place, row length 1024, one block of 256 threads per row.
// ---------------------------------------------------------------------------
__global__ void __launch_bounds__(256) softmax_rows(float* __restrict__ p)
{
    __shared__ float sh[8];
    long base = (long)blockIdx.x * SQ;
    int t = threadIdx.x;
    float4 v = *(float4*)&p[base + t * 4];

    float m = block_max256(fmaxf(fmaxf(v.x, v.y), fmaxf(v.z, v.w)), sh);
    float4 e;
    e.x = expf(v.x - m);
    e.y = expf(v.y - m);
    e.z = expf(v.z - m);
    e.w = expf(v.w - m);
    float s = block_sum256(e.x + e.y + e.z + e.w, sh);
    float inv = 1.0f / s;
    e.x *= inv; e.y *= inv; e.z *= inv; e.w *= inv;
    *(float4*)&p[base + t * 4] = e;
}

// ---------------------------------------------------------------------------
// out = LayerNorm(A + Bx) * g + b   (row length 1024, one block per row)
// ---------------------------------------------------------------------------
__global__ void __launch_bounds__(256) resid_ln(
    const float* __restrict__ A, const float* __restrict__ Bx,
    const float* __restrict__ gw, const float* __restrict__ bw,
    float* __restrict__ out)
{
    __shared__ float sh[8];
    long base = (long)blockIdx.x * DM;
    int t = threadIdx.x;
    float4 a = *(const float4*)&A[base + t * 4];
    float4 b = *(const float4*)&Bx[base + t * 4];
    float4 v = make_float4(a.x + b.x, a.y + b.y, a.z + b.z, a.w + b.w);

    float s = block_sum256(v.x + v.y + v.z + v.w, sh);
    float mu = s * (1.0f / DM);
    float dx = v.x - mu, dy = v.y - mu, dz = v.z - mu, dw = v.w - mu;
    float ss = block_sum256(dx * dx + dy * dy + dz * dz + dw * dw, sh);
    float rstd = rsqrtf(ss * (1.0f / DM) + 1e-6f);

    float4 g4 = *(const float4*)&gw[t * 4];
    float4 b4 = *(const float4*)&bw[t * 4];
    float4 o;
    o.x = dx * rstd * g4.x + b4.x;
    o.y = dy * rstd * g4.y + b4.y;
    o.z = dz * rstd * g4.z + b4.z;
    o.w = dw * rstd * g4.w + b4.w;
    *(float4*)&out[base + t * 4] = o;
}

// ---------------------------------------------------------------------------
// Launch
// ---------------------------------------------------------------------------
extern "C" void kernel_launch(void* const* d_in, const int* in_sizes, int n_in,
                              void* d_out, int out_size)
{
    const float* x_in      = (const float*)d_in[0];
    const int*   mask      = (const int*)  d_in[1];
    const float* attn_bias = (const float*)d_in[2];
    const float* Wq        = (const float*)d_in[3];
    const float* Wk        = (const float*)d_in[4];
    const float* Wv        = (const float*)d_in[5];
    const float* ln1_g     = (const float*)d_in[6];
    const float* ln1_b     = (const float*)d_in[7];
    const float* W1        = (const float*)d_in[8];
    const float* b1        = (const float*)d_in[9];
    const float* W2        = (const float*)d_in[10];
    const float* b2        = (const float*)d_in[11];
    const float* ln2_g     = (const float*)d_in[12];
    const float* ln2_b     = (const float*)d_in[13];

    float* out  = (float*)d_out;
    float* outx = out + (long)NL * BB * NH * SQ * SQ;

    float *gq, *gk, *gv, *gx, *gt, *gh;
    cudaGetSymbolAddress((void**)&gq, g_q);
    cudaGetSymbolAddress((void**)&gk, g_k);
    cudaGetSymbolAddress((void**)&gv, g_v);
    cudaGetSymbolAddress((void**)&gx, g_x);
    cudaGetSymbolAddress((void**)&gt, g_t);
    cudaGetSymbolAddress((void**)&gh, g_h);

    cudaMemcpyAsync(gx, x_in, sizeof(float) * BB * SQ * DM, cudaMemcpyDeviceToDevice);

    dim3 blk(256);
    const int M = BB * SQ;  // 2048

    for (int n = 0; n < NL; n++) {
        const float* wq = Wq + (long)n * DM * DM;
        const float* wk = Wk + (long)n * DM * DM;
        const float* wv = Wv + (long)n * DM * DM;
        float* p = out + (long)n * BB * NH * SQ * SQ;

        // QKV projections
        gemm_nn<0, 0><<<dim3(16, 32, 1), blk>>>(gx, wq, gq, nullptr, M, DM, DM, DM, DM, DM);
        gemm_nn<0, 0><<<dim3(16, 32, 1), blk>>>(gx, wk, gk, nullptr, M, DM, DM, DM, DM, DM);
        gemm_nn<0, 0><<<dim3(16, 32, 1), blk>>>(gx, wv, gv, nullptr, M, DM, DM, DM, DM, DM);

        // scores = q k^T * scale + bias, masked
        attn_scores<<<dim3(SQ / 64, SQ / 64, BB * NH), blk>>>(gq, gk, attn_bias, mask, p);

        // softmax rows (in place in output buffer)
        softmax_rows<<<BB * NH * SQ, blk>>>(p);

        // o = p @ v   (batched over b,h)
        gemm_nn<0, 1><<<dim3(1, SQ / 64, BB * NH), blk>>>(p, gv, gt, nullptr,
                                                          SQ, DK, SQ, SQ, DM, DM);

        // x = LN(o + x)
        resid_ln<<<M, blk>>>(gt, gx, ln1_g + (long)n * DM, ln1_b + (long)n * DM, gx);

        // h = gelu(x W1 + b1)
        gemm_nn<2, 0><<<dim3(32, 32, 1), blk>>>(gx, W1 + (long)n * DM * DFF, gh,
                                                b1 + (long)n * DFF, M, DFF, DM, DM, DFF, DFF);
        // f = h W2 + b2
        gemm_nn<1, 0><<<dim3(16, 32, 1), blk>>>(gh, W2 + (long)n * DFF * DM, gt,
                                                b2 + (long)n * DM, M, DM, DFF, DFF, DM, DM);
        // x = LN(x + f)
        resid_ln<<<M, blk>>>(gx, gt, ln2_g + (long)n * DM, ln2_b + (long)n * DM, gx);
    }

    cudaMemcpyAsync(outx, gx, sizeof(float) * BB * SQ * DM, cudaMemcpyDeviceToDevice);
}

// round 3
// speedup vs baseline: 1.6931x; 1.6931x over previous
#include <cuda_runtime.h>
#include <cuda_bf16.h>
#include <math.h>

// Problem constants
#define BB   2
#define SQ   1024
#define DM   1024
#define NH   16
#define DK   64
#define DFF  2048
#define NL   4

// ---------------------------------------------------------------------------
// Scratch (device globals — no allocation allowed)
// ---------------------------------------------------------------------------
__device__ __align__(16) float g_q[BB * SQ * DM];
__device__ __align__(16) float g_k[BB * SQ * DM];
__device__ __align__(16) float g_v[BB * SQ * DM];
__device__ __align__(16) float g_x[BB * SQ * DM];
__device__ __align__(16) float g_t[BB * SQ * DM];
__device__ __align__(16) float g_h[BB * SQ * DFF];

// ---------------------------------------------------------------------------
// Helpers
// ---------------------------------------------------------------------------
__device__ __forceinline__ unsigned f2tf(float f) {
    unsigned u;
    asm("cvt.rna.tf32.f32 %0, %1;" : "=r"(u) : "f"(f));
    return u;
}

__device__ __forceinline__ void mma8(float* c, const unsigned* a, const unsigned* b) {
    asm volatile(
        "mma.sync.aligned.m16n8k8.row.col.f32.tf32.tf32.f32 "
        "{%0,%1,%2,%3},{%4,%5,%6,%7},{%8,%9},{%0,%1,%2,%3};\n"
        : "+f"(c[0]), "+f"(c[1]), "+f"(c[2]), "+f"(c[3])
        : "r"(a[0]), "r"(a[1]), "r"(a[2]), "r"(a[3]), "r"(b[0]), "r"(b[1]));
}

__device__ __forceinline__ float gelu_tanh_f(float x) {
    float x3 = x * x * x;
    return 0.5f * x * (1.0f + tanhf(0.7978845608028654f * (x + 0.044715f * x3)));
}

__device__ __forceinline__ float block_sum256(float v, float* sh) {
    #pragma unroll
    for (int o = 16; o; o >>= 1) v += __shfl_xor_sync(0xffffffffu, v, o);
    int w = threadIdx.x >> 5;
    if ((threadIdx.x & 31) == 0) sh[w] = v;
    __syncthreads();
    float r = (threadIdx.x < 8) ? sh[threadIdx.x] : 0.0f;
    if (threadIdx.x < 32) {
        #pragma unroll
        for (int o = 4; o; o >>= 1) r += __shfl_xor_sync(0xffffffffu, r, o);
        if (threadIdx.x == 0) sh[0] = r;
    }
    __syncthreads();
    r = sh[0];
    __syncthreads();
    return r;
}

// ---------------------------------------------------------------------------
// tf32 tensor-core GEMM: C[M,N] = A[M,K] * B[K,N] (+bias)(+gelu)
// Block tile 128x64, BK=32, 256 threads = 8 warps (4x2), warp tile 32x32.
// EPI: 0 none, 1 +bias, 2 +bias+gelu
// ATTN: blockIdx.z = b*NH+h; A += z*SQ*SQ; B,C += b*SQ*DM + h*DK  (PV gemm)
// ---------------------------------------------------------------------------
template<int EPI, int ATTN>
__global__ void __launch_bounds__(256) gemm_tf32(
    const float* __restrict__ A, const float* __restrict__ Bm,
    float* __restrict__ C, const float* __restrict__ bias,
    int M, int N, int K, int lda, int ldb, int ldc)
{
    if (ATTN) {
        int z = blockIdx.z;
        int b = z >> 4;
        int h = z & 15;
        A  += (long)z * SQ * SQ;
        Bm += (long)b * SQ * DM + h * DK;
        C  += (long)b * SQ * DM + h * DK;
    }
    __shared__ unsigned As[128][36];   // [row][k], pad 4 -> conflict-free frags
    __shared__ unsigned Bs[64][36];    // [n][k] (transposed store)

    int t = threadIdx.x;
    int lane = t & 31, w = t >> 5;
    int wm = w >> 1, wn = w & 1;
    int lq = lane >> 2, lr = lane & 3;
    int row0 = blockIdx.y * 128, col0 = blockIdx.x * 64;

    float acc[2][4][4];
    #pragma unroll
    for (int i = 0; i < 2; i++)
        #pragma unroll
        for (int j = 0; j < 4; j++)
            #pragma unroll
            for (int l = 0; l < 4; l++) acc[i][j][l] = 0.0f;

    for (int k0 = 0; k0 < K; k0 += 32) {
        // Load A tile 128x32
        #pragma unroll
        for (int i = 0; i < 4; i++) {
            int idx = t + i * 256;          // 0..1023
            int row = idx >> 3;             // 0..127
            int kc  = (idx & 7) * 4;
            float4 v = *(const float4*)&A[(long)(row0 + row) * lda + k0 + kc];
            unsigned* dst = &As[row][kc];
            dst[0] = f2tf(v.x); dst[1] = f2tf(v.y);
            dst[2] = f2tf(v.z); dst[3] = f2tf(v.w);
        }
        // Load B tile 32x64, store transposed [n][k]
        #pragma unroll
        for (int i = 0; i < 2; i++) {
            int idx = t + i * 256;          // 0..511
            int krow = idx >> 4;            // 0..31
            int nc = (idx & 15) * 4;
            float4 v = *(const float4*)&Bm[(long)(k0 + krow) * ldb + col0 + nc];
            Bs[nc + 0][krow] = f2tf(v.x);
            Bs[nc + 1][krow] = f2tf(v.y);
            Bs[nc + 2][krow] = f2tf(v.z);
            Bs[nc + 3][krow] = f2tf(v.w);
        }
        __syncthreads();

        #pragma unroll
        for (int ks = 0; ks < 4; ks++) {
            int kb = ks * 8;
            unsigned a[2][4], bf[4][2];
            #pragma unroll
            for (int mi = 0; mi < 2; mi++) {
                int ar = wm * 32 + mi * 16 + lq;
                a[mi][0] = As[ar][kb + lr];
                a[mi][1] = As[ar + 8][kb + lr];
                a[mi][2] = As[ar][kb + 4 + lr];
                a[mi][3] = As[ar + 8][kb + 4 + lr];
            }
            #pragma unroll
            for (int nj = 0; nj < 4; nj++) {
                int bn = wn * 32 + nj * 8 + lq;
                bf[nj][0] = Bs[bn][kb + lr];
                bf[nj][1] = Bs[bn][kb + 4 + lr];
            }
            #pragma unroll
            for (int mi = 0; mi < 2; mi++)
                #pragma unroll
                for (int nj = 0; nj < 4; nj++)
                    mma8(acc[mi][nj], a[mi], bf[nj]);
        }
        __syncthreads();
    }

    // Epilogue
    #pragma unroll
    for (int mi = 0; mi < 2; mi++) {
        #pragma unroll
        for (int nj = 0; nj < 4; nj++) {
            int r = row0 + wm * 32 + mi * 16 + lq;
            int c = col0 + wn * 32 + nj * 8 + 2 * lr;
            float v0 = acc[mi][nj][0], v1 = acc[mi][nj][1];
            float v2 = acc[mi][nj][2], v3 = acc[mi][nj][3];
            if (EPI >= 1) {
                float b0 = bias[c], b1 = bias[c + 1];
                v0 += b0; v1 += b1; v2 += b0; v3 += b1;
            }
            if (EPI == 2) {
                v0 = gelu_tanh_f(v0); v1 = gelu_tanh_f(v1);
                v2 = gelu_tanh_f(v2); v3 = gelu_tanh_f(v3);
            }
            *(float2*)&C[(long)r * ldc + c] = make_float2(v0, v1);
            *(float2*)&C[(long)(r + 8) * ldc + c] = make_float2(v2, v3);
        }
    }
}

// ---------------------------------------------------------------------------
// Fused scores + softmax. One block = (z, 32 q-rows) x all 1024 keys.
// Q tile resident (tf32), K streamed in 8 slabs of 128 keys, scores in SMEM,
// softmax in SMEM, p written once.
// grid: (SQ/32, B*NH), 256 threads.
// ---------------------------------------------------------------------------
#define SC_SMEM_WORDS (32 * 68 + 128 * 68 + 32 * 1032 + 1024)

__global__ void __launch_bounds__(256) attn_scores_softmax(
    const float* __restrict__ q, const float* __restrict__ k,
    const float* __restrict__ bias, const int* __restrict__ mask,
    float* __restrict__ p)
{
    extern __shared__ char sm_raw[];
    unsigned* Qs = (unsigned*)sm_raw;            // [32][68]
    unsigned* Ks = Qs + 32 * 68;                 // [128][68]
    float*    Ss = (float*)(Ks + 128 * 68);      // [32][1032]
    int*      msk = (int*)(Ss + 32 * 1032);      // [1024]

    int t = threadIdx.x;
    int lane = t & 31, w = t >> 5;
    int lq = lane >> 2, lr = lane & 3;
    int z = blockIdx.y, b = z >> 4, h = z & 15;
    int q0 = blockIdx.x * 32;

    const float* qb = q + (long)b * SQ * DM + h * DK;
    const float* kb = k + (long)b * SQ * DM + h * DK;

    // Load Q tile 32x64 (tf32)
    #pragma unroll
    for (int i = 0; i < 2; i++) {
        int idx = t + i * 256;
        int row = idx >> 4;
        int kc = (idx & 15) * 4;
        float4 v = *(const float4*)&qb[(long)(q0 + row) * DM + kc];
        unsigned* dst = &Qs[row * 68 + kc];
        dst[0] = f2tf(v.x); dst[1] = f2tf(v.y);
        dst[2] = f2tf(v.z); dst[3] = f2tf(v.w);
    }
    {
        int4 mv = ((const int4*)(mask + b * SQ))[t];
        *(int4*)&msk[t * 4] = mv;
    }

    // Phase 1: raw scores (Q.K^T) into Ss
    for (int slab = 0; slab < 8; slab++) {
        int key0 = slab * 128;
        #pragma unroll
        for (int i = 0; i < 8; i++) {
            int idx = t + i * 256;
            int row = idx >> 4;
            int kc = (idx & 15) * 4;
            float4 v = *(const float4*)&kb[(long)(key0 + row) * DM + kc];
            unsigned* dst = &Ks[row * 68 + kc];
            dst[0] = f2tf(v.x); dst[1] = f2tf(v.y);
            dst[2] = f2tf(v.z); dst[3] = f2tf(v.w);
        }
        __syncthreads();

        float acc[2][2][4];
        #pragma unroll
        for (int i = 0; i < 2; i++)
            #pragma unroll
            for (int j = 0; j < 2; j++)
                #pragma unroll
                for (int l = 0; l < 4; l++) acc[i][j][l] = 0.0f;

        #pragma unroll
        for (int ks = 0; ks < 8; ks++) {
            int kv = ks * 8;
            unsigned a[2][4], bf[2][2];
            #pragma unroll
            for (int mi = 0; mi < 2; mi++) {
                int ar = mi * 16 + lq;
                a[mi][0] = Qs[ar * 68 + kv + lr];
                a[mi][1] = Qs[(ar + 8) * 68 + kv + lr];
                a[mi][2] = Qs[ar * 68 + kv + 4 + lr];
                a[mi][3] = Qs[(ar + 8) * 68 + kv + 4 + lr];
            }
            #pragma unroll
            for (int nj = 0; nj < 2; nj++) {
                int kr = w * 16 + nj * 8 + lq;
                bf[nj][0] = Ks[kr * 68 + kv + lr];
                bf[nj][1] = Ks[kr * 68 + kv + 4 + lr];
            }
            #pragma unroll
            for (int mi = 0; mi < 2; mi++)
                #pragma unroll
                for (int nj = 0; nj < 2; nj++)
                    mma8(acc[mi][nj], a[mi], bf[nj]);
        }

        #pragma unroll
        for (int mi = 0; mi < 2; mi++) {
            #pragma unroll
            for (int nj = 0; nj < 2; nj++) {
                int r = mi * 16 + lq;
                int c = key0 + w * 16 + nj * 8 + 2 * lr;
                Ss[r * 1032 + c]     = acc[mi][nj][0];
                Ss[r * 1032 + c + 1] = acc[mi][nj][1];
                Ss[(r + 8) * 1032 + c]     = acc[mi][nj][2];
                Ss[(r + 8) * 1032 + c + 1] = acc[mi][nj][3];
            }
        }
        __syncthreads();
    }

    // Phase 2: softmax. Warp w owns rows w*4 .. w*4+3.
    for (int rr = 0; rr < 4; rr++) {
        int r = w * 4 + rr;
        long qi = q0 + r;
        const float* brow = bias + ((long)z * SQ + qi) * SQ;
        float* srow = &Ss[r * 1032];

        float m = -3.4e38f;
        #pragma unroll 4
        for (int i = 0; i < 32; i++) {
            int c = i * 32 + lane;
            float v = srow[c] * 0.125f + __ldg(&brow[c]);
            if (msk[c] == 0) v = -9e15f;
            srow[c] = v;
            m = fmaxf(m, v);
        }
        #pragma unroll
        for (int o = 16; o; o >>= 1) m = fmaxf(m, __shfl_xor_sync(0xffffffffu, m, o));

        float s = 0.0f;
        #pragma unroll 4
        for (int i = 0; i < 32; i++) {
            int c = i * 32 + lane;
            float e = __expf(srow[c] - m);
            s += e;
            srow[c] = e;
        }
        #pragma unroll
        for (int o = 16; o; o >>= 1) s += __shfl_xor_sync(0xffffffffu, s, o);
        float inv = 1.0f / s;

        float* prow = p + ((long)z * SQ + qi) * SQ;
        #pragma unroll 4
        for (int i = 0; i < 32; i++) {
            int c = i * 32 + lane;
            prow[c] = srow[c] * inv;
        }
    }
}

// ---------------------------------------------------------------------------
// out = LayerNorm(A + Bx) * g + b   (row length 1024, one block per row)
// ---------------------------------------------------------------------------
__global__ void __launch_bounds__(256) resid_ln(
    const float* __restrict__ A, const float* __restrict__ Bx,
    const float* __restrict__ gw, const float* __restrict__ bw,
    float* __restrict__ out)
{
    __shared__ float sh[8];
    long base = (long)blockIdx.x * DM;
    int t = threadIdx.x;
    float4 a = *(const float4*)&A[base + t * 4];
    float4 b = *(const float4*)&Bx[base + t * 4];
    float4 v = make_float4(a.x + b.x, a.y + b.y, a.z + b.z, a.w + b.w);

    float s = block_sum256(v.x + v.y + v.z + v.w, sh);
    float mu = s * (1.0f / DM);
    float dx = v.x - mu, dy = v.y - mu, dz = v.z - mu, dw = v.w - mu;
    float ss = block_sum256(dx * dx + dy * dy + dz * dz + dw * dw, sh);
    float rstd = rsqrtf(ss * (1.0f / DM) + 1e-6f);

    float4 g4 = *(const float4*)&gw[t * 4];
    float4 b4 = *(const float4*)&bw[t * 4];
    float4 o;
    o.x = dx * rstd * g4.x + b4.x;
    o.y = dy * rstd * g4.y + b4.y;
    o.z = dz * rstd * g4.z + b4.z;
    o.w = dw * rstd * g4.w + b4.w;
    *(float4*)&out[base + t * 4] = o;
}

// ---------------------------------------------------------------------------
// Launch
// ---------------------------------------------------------------------------
extern "C" void kernel_launch(void* const* d_in, const int* in_sizes, int n_in,
                              void* d_out, int out_size)
{
    const float* x_in      = (const float*)d_in[0];
    const int*   mask      = (const int*)  d_in[1];
    const float* attn_bias = (const float*)d_in[2];
    const float* Wq        = (const float*)d_in[3];
    const float* Wk        = (const float*)d_in[4];
    const float* Wv        = (const float*)d_in[5];
    const float* ln1_g     = (const float*)d_in[6];
    const float* ln1_b     = (const float*)d_in[7];
    const float* W1        = (const float*)d_in[8];
    const float* b1        = (const float*)d_in[9];
    const float* W2        = (const float*)d_in[10];
    const float* b2        = (const float*)d_in[11];
    const float* ln2_g     = (const float*)d_in[12];
    const float* ln2_b     = (const float*)d_in[13];

    float* out  = (float*)d_out;
    float* outx = out + (long)NL * BB * NH * SQ * SQ;

    float *gq, *gk, *gv, *gx, *gt, *gh;
    cudaGetSymbolAddress((void**)&gq, g_q);
    cudaGetSymbolAddress((void**)&gk, g_k);
    cudaGetSymbolAddress((void**)&gv, g_v);
    cudaGetSymbolAddress((void**)&gx, g_x);
    cudaGetSymbolAddress((void**)&gt, g_t);
    cudaGetSymbolAddress((void**)&gh, g_h);

    static int smem_set = 0;
    if (!smem_set) {
        cudaFuncSetAttribute(attn_scores_softmax,
                             cudaFuncAttributeMaxDynamicSharedMemorySize,
                             SC_SMEM_WORDS * 4);
        smem_set = 1;
    }

    cudaMemcpyAsync(gx, x_in, sizeof(float) * BB * SQ * DM, cudaMemcpyDeviceToDevice);

    dim3 blk(256);
    const int M = BB * SQ;  // 2048

    for (int n = 0; n < NL; n++) {
        const float* wq = Wq + (long)n * DM * DM;
        const float* wk = Wk + (long)n * DM * DM;
        const float* wv = Wv + (long)n * DM * DM;
        float* p = out + (long)n * BB * NH * SQ * SQ;

        // QKV projections (tf32 tensor cores)
        gemm_tf32<0, 0><<<dim3(16, 16, 1), blk>>>(gx, wq, gq, nullptr, M, DM, DM, DM, DM, DM);
        gemm_tf32<0, 0><<<dim3(16, 16, 1), blk>>>(gx, wk, gk, nullptr, M, DM, DM, DM, DM, DM);
        gemm_tf32<0, 0><<<dim3(16, 16, 1), blk>>>(gx, wv, gv, nullptr, M, DM, DM, DM, DM, DM);

        // fused scores + softmax -> p (written once)
        attn_scores_softmax<<<dim3(SQ / 32, BB * NH), blk, SC_SMEM_WORDS * 4>>>(
            gq, gk, attn_bias, mask, p);

        // o = p @ v   (batched over b,h)
        gemm_tf32<0, 1><<<dim3(1, SQ / 128, BB * NH), blk>>>(p, gv, gt, nullptr,
                                                             SQ, DK, SQ, SQ, DM, DM);

        // x = LN(o + x)
        resid_ln<<<M, blk>>>(gt, gx, ln1_g + (long)n * DM, ln1_b + (long)n * DM, gx);

        // h = gelu(x W1 + b1)
        gemm_tf32<2, 0><<<dim3(32, 16, 1), blk>>>(gx, W1 + (long)n * DM * DFF, gh,
                                                  b1 + (long)n * DFF, M, DFF, DM, DM, DFF, DFF);
        // f = h W2 + b2
        gemm_tf32<1, 0><<<dim3(16, 16, 1), blk>>>(gh, W2 + (long)n * DFF * DM, gt,
                                                  b2 + (long)n * DM, M, DM, DFF, DFF, DM, DM);
        // x = LN(x + f)
        resid_ln<<<M, blk>>>(gx, gt, ln2_g + (long)n * DM, ln2_b + (long)n * DM, gx);
    }

    cudaMemcpyAsync(outx, gx, sizeof(float) * BB * SQ * DM, cudaMemcpyDeviceToDevice);
}

// round 5
// speedup vs baseline: 2.7714x; 1.6369x over previous
#include <cuda_runtime.h>
#include <cuda_bf16.h>
#include <math.h>

// Problem constants
#define BB   2
#define SQ   1024
#define DM   1024
#define NH   16
#define DK   64
#define DFF  2048
#define NL   4

// ---------------------------------------------------------------------------
// Scratch (device globals — no allocation allowed)
// ---------------------------------------------------------------------------
__device__ __align__(16) float g_q[BB * SQ * DM];
__device__ __align__(16) float g_k[BB * SQ * DM];
__device__ __align__(16) float g_v[BB * SQ * DM];
__device__ __align__(16) float g_x[BB * SQ * DM];
__device__ __align__(16) float g_t[BB * SQ * DM];
__device__ __align__(16) float g_h[BB * SQ * DFF];

// ---------------------------------------------------------------------------
// Helpers
// ---------------------------------------------------------------------------
__device__ __forceinline__ unsigned f2tf(float f) {
    unsigned u;
    asm("cvt.rna.tf32.f32 %0, %1;" : "=r"(u) : "f"(f));
    return u;
}

__device__ __forceinline__ void mma8(float* c, const unsigned* a, const unsigned* b) {
    asm volatile(
        "mma.sync.aligned.m16n8k8.row.col.f32.tf32.tf32.f32 "
        "{%0,%1,%2,%3},{%4,%5,%6,%7},{%8,%9},{%0,%1,%2,%3};\n"
        : "+f"(c[0]), "+f"(c[1]), "+f"(c[2]), "+f"(c[3])
        : "r"(a[0]), "r"(a[1]), "r"(a[2]), "r"(a[3]), "r"(b[0]), "r"(b[1]));
}

__device__ __forceinline__ void cpa16(float* smem_dst, const float* gsrc) {
    unsigned s = (unsigned)__cvta_generic_to_shared(smem_dst);
    asm volatile("cp.async.cg.shared.global [%0], [%1], 16;" :: "r"(s), "l"(gsrc));
}
__device__ __forceinline__ void cpa_commit() {
    asm volatile("cp.async.commit_group;" ::: "memory");
}
__device__ __forceinline__ void cpa_wait1() {
    asm volatile("cp.async.wait_group 1;" ::: "memory");
}
__device__ __forceinline__ void cpa_wait0() {
    asm volatile("cp.async.wait_group 0;" ::: "memory");
}

__device__ __forceinline__ float gelu_tanh_f(float x) {
    float x3 = x * x * x;
    return 0.5f * x * (1.0f + tanhf(0.7978845608028654f * (x + 0.044715f * x3)));
}

__device__ __forceinline__ float block_sum256(float v, float* sh) {
    #pragma unroll
    for (int o = 16; o; o >>= 1) v += __shfl_xor_sync(0xffffffffu, v, o);
    int w = threadIdx.x >> 5;
    if ((threadIdx.x & 31) == 0) sh[w] = v;
    __syncthreads();
    float r = (threadIdx.x < 8) ? sh[threadIdx.x] : 0.0f;
    if (threadIdx.x < 32) {
        #pragma unroll
        for (int o = 4; o; o >>= 1) r += __shfl_xor_sync(0xffffffffu, r, o);
        if (threadIdx.x == 0) sh[0] = r;
    }
    __syncthreads();
    r = sh[0];
    __syncthreads();
    return r;
}

// ---------------------------------------------------------------------------
// tf32 tensor-core GEMM with cp.async 2-stage pipeline.
// C[M,N] = A[M,K] * B[K,N] (+bias)(+gelu)
// Block tile 128x64, BK=32, 256 threads = 8 warps (4x2), warp tile 32x32.
// Dynamic smem: As[2][128][36] floats, Bs[2][32][72] floats (natural layouts).
// EPI: 0 none, 1 +bias, 2 +bias+gelu
// ATTN: blockIdx.z = b*NH+h; A += z*SQ*SQ; B,C += b*SQ*DM + h*DK  (PV gemm)
// ---------------------------------------------------------------------------
#define GEMM_SMEM_BYTES ((2 * 128 * 36 + 2 * 32 * 72) * 4)

template<int EPI, int ATTN>
__global__ void __launch_bounds__(256) gemm_tf32(
    const float* __restrict__ A, const float* __restrict__ Bm,
    float* __restrict__ C, const float* __restrict__ bias,
    int M, int N, int K, int lda, int ldb, int ldc)
{
    if (ATTN) {
        int z = blockIdx.z;
        int b = z >> 4;
        int h = z & 15;
        A  += (long)z * SQ * SQ;
        Bm += (long)b * SQ * DM + h * DK;
        C  += (long)b * SQ * DM + h * DK;
    }
    extern __shared__ float dsm[];
    float* As = dsm;                 // [2][128][36]
    float* Bs = dsm + 2 * 128 * 36;  // [2][32][72]

    int t = threadIdx.x;
    int lane = t & 31, w = t >> 5;
    int wm = w >> 1, wn = w & 1;
    int lq = lane >> 2, lr = lane & 3;
    int row0 = blockIdx.y * 128, col0 = blockIdx.x * 64;

    float acc[2][4][4];
    #pragma unroll
    for (int i = 0; i < 2; i++)
        #pragma unroll
        for (int j = 0; j < 4; j++)
            #pragma unroll
            for (int l = 0; l < 4; l++) acc[i][j][l] = 0.0f;

    // cp.async tile loaders
    int a_row = t >> 3;             // 0..31 (x4 iters -> 128)
    int a_kc  = (t & 7) * 4;
    int b_kr  = t >> 4;             // 0..15 (x2 iters -> 32)
    int b_nc  = (t & 15) * 4;

    #define LOAD_TILES(s, k0)                                                   \
        {                                                                       \
            _Pragma("unroll")                                                   \
            for (int i = 0; i < 4; i++) {                                       \
                int row = a_row + i * 32;                                       \
                cpa16(&As[(s) * 4608 + row * 36 + a_kc],                        \
                      &A[(long)(row0 + row) * lda + (k0) + a_kc]);              \
            }                                                                   \
            _Pragma("unroll")                                                   \
            for (int i = 0; i < 2; i++) {                                       \
                int kr = b_kr + i * 16;                                         \
                cpa16(&Bs[(s) * 2304 + kr * 72 + b_nc],                         \
                      &Bm[(long)((k0) + kr) * ldb + col0 + b_nc]);              \
            }                                                                   \
        }

    LOAD_TILES(0, 0);
    cpa_commit();

    int KT = K >> 5;
    for (int kt = 0; kt < KT; kt++) {
        int cur = kt & 1;
        if (kt + 1 < KT) {
            LOAD_TILES(cur ^ 1, (kt + 1) * 32);
            cpa_commit();
            cpa_wait1();
        } else {
            cpa_wait0();
        }
        __syncthreads();

        const float* Ac = &As[cur * 4608];
        const float* Bc = &Bs[cur * 2304];
        #pragma unroll
        for (int ks = 0; ks < 4; ks++) {
            int kb = ks * 8;
            unsigned a[2][4], bf[4][2];
            #pragma unroll
            for (int mi = 0; mi < 2; mi++) {
                int ar = wm * 32 + mi * 16 + lq;
                a[mi][0] = f2tf(Ac[ar * 36 + kb + lr]);
                a[mi][1] = f2tf(Ac[(ar + 8) * 36 + kb + lr]);
                a[mi][2] = f2tf(Ac[ar * 36 + kb + 4 + lr]);
                a[mi][3] = f2tf(Ac[(ar + 8) * 36 + kb + 4 + lr]);
            }
            #pragma unroll
            for (int nj = 0; nj < 4; nj++) {
                int bn = wn * 32 + nj * 8 + lq;
                bf[nj][0] = f2tf(Bc[(kb + lr) * 72 + bn]);
                bf[nj][1] = f2tf(Bc[(kb + 4 + lr) * 72 + bn]);
            }
            #pragma unroll
            for (int mi = 0; mi < 2; mi++)
                #pragma unroll
                for (int nj = 0; nj < 4; nj++)
                    mma8(acc[mi][nj], a[mi], bf[nj]);
        }
        __syncthreads();
    }
    #undef LOAD_TILES

    // Epilogue
    #pragma unroll
    for (int mi = 0; mi < 2; mi++) {
        #pragma unroll
        for (int nj = 0; nj < 4; nj++) {
            int r = row0 + wm * 32 + mi * 16 + lq;
            int c = col0 + wn * 32 + nj * 8 + 2 * lr;
            float v0 = acc[mi][nj][0], v1 = acc[mi][nj][1];
            float v2 = acc[mi][nj][2], v3 = acc[mi][nj][3];
            if (EPI >= 1) {
                float b0 = bias[c], b1 = bias[c + 1];
                v0 += b0; v1 += b1; v2 += b0; v3 += b1;
            }
            if (EPI == 2) {
                v0 = gelu_tanh_f(v0); v1 = gelu_tanh_f(v1);
                v2 = gelu_tanh_f(v2); v3 = gelu_tanh_f(v3);
            }
            *(float2*)&C[(long)r * ldc + c] = make_float2(v0, v1);
            *(float2*)&C[(long)(r + 8) * ldc + c] = make_float2(v2, v3);
        }
    }
}

// ---------------------------------------------------------------------------
// Fused scores + softmax, v2.
// Block = (z, 32 q-rows) x all 1024 keys. 512 threads = 16 warps.
// K streamed in 8 slabs of 128 keys, double-buffered cp.async.
// bias+scale+mask folded into slab epilogue. Softmax in SMEM, p written once.
// grid: (SQ/32, B*NH).
// ---------------------------------------------------------------------------
#define SC_SMEM_BYTES ((32 * 68 + 2 * 128 * 68 + 32 * 1032 + 1024) * 4)

__global__ void __launch_bounds__(512) attn_scores_softmax(
    const float* __restrict__ q, const float* __restrict__ k,
    const float* __restrict__ bias, const int* __restrict__ mask,
    float* __restrict__ p)
{
    extern __shared__ char smx[];
    unsigned* Qs = (unsigned*)smx;               // [32][68] tf32
    float* Ks = (float*)(Qs + 32 * 68);          // [2][128][68] raw floats
    float* Ss = Ks + 2 * 128 * 68;               // [32][1032]
    int* msk = (int*)(Ss + 32 * 1032);           // [1024]

    int t = threadIdx.x;
    int lane = t & 31, w = t >> 5;               // 16 warps
    int lq = lane >> 2, lr = lane & 3;
    int z = blockIdx.y, b = z >> 4, h = z & 15;
    int q0 = blockIdx.x * 32;

    const float* qb = q + (long)b * SQ * DM + h * DK;
    const float* kb = k + (long)b * SQ * DM + h * DK;
    const float* bz = bias + (long)z * SQ * SQ;

    // K slab cp.async loader: 128 rows x 64 floats = 2048 float4, 512 thr x 4
    int k_row = t >> 4;             // 0..31 (x4 -> 128)
    int k_kc  = (t & 15) * 4;
    #define LOAD_SLAB(s, key0)                                                  \
        {                                                                       \
            _Pragma("unroll")                                                   \
            for (int i = 0; i < 4; i++) {                                       \
                int row = k_row + i * 32;                                       \
                cpa16(&Ks[(s) * 8704 + row * 68 + k_kc],                        \
                      &kb[(long)((key0) + row) * DM + k_kc]);                   \
            }                                                                   \
        }

    LOAD_SLAB(0, 0);
    cpa_commit();

    // Q tile 32x64 -> tf32 smem (one float4 per thread)
    {
        int row = t >> 4;
        int kc = (t & 15) * 4;
        float4 v = *(const float4*)&qb[(long)(q0 + row) * DM + kc];
        unsigned* dst = &Qs[row * 68 + kc];
        dst[0] = f2tf(v.x); dst[1] = f2tf(v.y);
        dst[2] = f2tf(v.z); dst[3] = f2tf(v.w);
    }
    if (t < 256) ((int4*)msk)[t] = ((const int4*)(mask + b * SQ))[t];

    // Phase 1: scores. Warp w owns keys [w*8, w*8+8) of each slab.
    for (int slab = 0; slab < 8; slab++) {
        int cur = slab & 1;
        int key0 = slab * 128;
        if (slab + 1 < 8) {
            LOAD_SLAB(cur ^ 1, key0 + 128);
            cpa_commit();
            cpa_wait1();
        } else {
            cpa_wait0();
        }
        __syncthreads();

        float acc[2][4];
        #pragma unroll
        for (int i = 0; i < 2; i++)
            #pragma unroll
            for (int l = 0; l < 4; l++) acc[i][l] = 0.0f;

        const float* Kc = &Ks[cur * 8704];
        #pragma unroll
        for (int ks = 0; ks < 8; ks++) {
            int kv = ks * 8;
            unsigned a[2][4], bf[2];
            #pragma unroll
            for (int mi = 0; mi < 2; mi++) {
                int ar = mi * 16 + lq;
                a[mi][0] = Qs[ar * 68 + kv + lr];
                a[mi][1] = Qs[(ar + 8) * 68 + kv + lr];
                a[mi][2] = Qs[ar * 68 + kv + 4 + lr];
                a[mi][3] = Qs[(ar + 8) * 68 + kv + 4 + lr];
            }
            int kn = w * 8 + lq;
            bf[0] = f2tf(Kc[kn * 68 + kv + lr]);
            bf[1] = f2tf(Kc[kn * 68 + kv + 4 + lr]);
            #pragma unroll
            for (int mi = 0; mi < 2; mi++)
                mma8(acc[mi], a[mi], bf);
        }

        // slab epilogue: scale + bias + mask -> Ss
        int c = key0 + w * 8 + 2 * lr;
        int m0 = msk[c], m1 = msk[c + 1];
        #pragma unroll
        for (int mi = 0; mi < 2; mi++) {
            #pragma unroll
            for (int half = 0; half < 2; half++) {
                int r = mi * 16 + half * 8 + lq;
                float2 bv = *(const float2*)&bz[(long)(q0 + r) * SQ + c];
                float v0 = acc[mi][half * 2 + 0] * 0.125f + bv.x;
                float v1 = acc[mi][half * 2 + 1] * 0.125f + bv.y;
                if (m0 == 0) v0 = -9e15f;
                if (m1 == 0) v1 = -9e15f;
                *(float2*)&Ss[r * 1032 + c] = make_float2(v0, v1);
            }
        }
        __syncthreads();
    }
    #undef LOAD_SLAB

    // Phase 2: softmax. Warp w owns rows w*2, w*2+1.
    #pragma unroll
    for (int rr = 0; rr < 2; rr++) {
        int r = w * 2 + rr;
        long qi = q0 + r;
        float* srow = &Ss[r * 1032];

        float4 vv[8];
        float m = -3.4e38f;
        #pragma unroll
        for (int i = 0; i < 8; i++) {
            vv[i] = *(float4*)&srow[(i * 32 + lane) * 4];
            m = fmaxf(m, fmaxf(fmaxf(vv[i].x, vv[i].y), fmaxf(vv[i].z, vv[i].w)));
        }
        #pragma unroll
        for (int o = 16; o; o >>= 1) m = fmaxf(m, __shfl_xor_sync(0xffffffffu, m, o));

        float s = 0.0f;
        #pragma unroll
        for (int i = 0; i < 8; i++) {
            vv[i].x = __expf(vv[i].x - m);
            vv[i].y = __expf(vv[i].y - m);
            vv[i].z = __expf(vv[i].z - m);
            vv[i].w = __expf(vv[i].w - m);
            s += vv[i].x + vv[i].y + vv[i].z + vv[i].w;
        }
        #pragma unroll
        for (int o = 16; o; o >>= 1) s += __shfl_xor_sync(0xffffffffu, s, o);
        float inv = 1.0f / s;

        float* prow = p + ((long)z * SQ + qi) * SQ;
        #pragma unroll
        for (int i = 0; i < 8; i++) {
            float4 e = make_float4(vv[i].x * inv, vv[i].y * inv,
                                   vv[i].z * inv, vv[i].w * inv);
            *(float4*)&prow[(i * 32 + lane) * 4] = e;
        }
    }
}

// ---------------------------------------------------------------------------
// out = LayerNorm(A + Bx) * g + b   (row length 1024, one block per row)
// ---------------------------------------------------------------------------
__global__ void __launch_bounds__(256) resid_ln(
    const float* __restrict__ A, const float* __restrict__ Bx,
    const float* __restrict__ gw, const float* __restrict__ bw,
    float* __restrict__ out)
{
    __shared__ float sh[8];
    long base = (long)blockIdx.x * DM;
    int t = threadIdx.x;
    float4 a = *(const float4*)&A[base + t * 4];
    float4 b = *(const float4*)&Bx[base + t * 4];
    float4 v = make_float4(a.x + b.x, a.y + b.y, a.z + b.z, a.w + b.w);

    float s = block_sum256(v.x + v.y + v.z + v.w, sh);
    float mu = s * (1.0f / DM);
    float dx = v.x - mu, dy = v.y - mu, dz = v.z - mu, dw = v.w - mu;
    float ss = block_sum256(dx * dx + dy * dy + dz * dz + dw * dw, sh);
    float rstd = rsqrtf(ss * (1.0f / DM) + 1e-6f);

    float4 g4 = *(const float4*)&gw[t * 4];
    float4 b4 = *(const float4*)&bw[t * 4];
    float4 o;
    o.x = dx * rstd * g4.x + b4.x;
    o.y = dy * rstd * g4.y + b4.y;
    o.z = dz * rstd * g4.z + b4.z;
    o.w = dw * rstd * g4.w + b4.w;
    *(float4*)&out[base + t * 4] = o;
}

// ---------------------------------------------------------------------------
// Launch
// ---------------------------------------------------------------------------
extern "C" void kernel_launch(void* const* d_in, const int* in_sizes, int n_in,
                              void* d_out, int out_size)
{
    const float* x_in      = (const float*)d_in[0];
    const int*   mask      = (const int*)  d_in[1];
    const float* attn_bias = (const float*)d_in[2];
    const float* Wq        = (const float*)d_in[3];
    const float* Wk        = (const float*)d_in[4];
    const float* Wv        = (const float*)d_in[5];
    const float* ln1_g     = (const float*)d_in[6];
    const float* ln1_b     = (const float*)d_in[7];
    const float* W1        = (const float*)d_in[8];
    const float* b1        = (const float*)d_in[9];
    const float* W2        = (const float*)d_in[10];
    const float* b2        = (const float*)d_in[11];
    const float* ln2_g     = (const float*)d_in[12];
    const float* ln2_b     = (const float*)d_in[13];

    float* out  = (float*)d_out;
    float* outx = out + (long)NL * BB * NH * SQ * SQ;

    float *gq, *gk, *gv, *gx, *gt, *gh;
    cudaGetSymbolAddress((void**)&gq, g_q);
    cudaGetSymbolAddress((void**)&gk, g_k);
    cudaGetSymbolAddress((void**)&gv, g_v);
    cudaGetSymbolAddress((void**)&gx, g_x);
    cudaGetSymbolAddress((void**)&gt, g_t);
    cudaGetSymbolAddress((void**)&gh, g_h);

    static int smem_set = 0;
    if (!smem_set) {
        cudaFuncSetAttribute(attn_scores_softmax,
                             cudaFuncAttributeMaxDynamicSharedMemorySize, SC_SMEM_BYTES);
        cudaFuncSetAttribute(gemm_tf32<0, 0>,
                             cudaFuncAttributeMaxDynamicSharedMemorySize, GEMM_SMEM_BYTES);
        cudaFuncSetAttribute(gemm_tf32<0, 1>,
                             cudaFuncAttributeMaxDynamicSharedMemorySize, GEMM_SMEM_BYTES);
        cudaFuncSetAttribute(gemm_tf32<1, 0>,
                             cudaFuncAttributeMaxDynamicSharedMemorySize, GEMM_SMEM_BYTES);
        cudaFuncSetAttribute(gemm_tf32<2, 0>,
                             cudaFuncAttributeMaxDynamicSharedMemorySize, GEMM_SMEM_BYTES);
        smem_set = 1;
    }

    cudaMemcpyAsync(gx, x_in, sizeof(float) * BB * SQ * DM, cudaMemcpyDeviceToDevice);

    dim3 blk(256);
    const int M = BB * SQ;  // 2048

    for (int n = 0; n < NL; n++) {
        const float* wq = Wq + (long)n * DM * DM;
        const float* wk = Wk + (long)n * DM * DM;
        const float* wv = Wv + (long)n * DM * DM;
        float* p = out + (long)n * BB * NH * SQ * SQ;

        // QKV projections (tf32 tensor cores, cp.async pipelined)
        gemm_tf32<0, 0><<<dim3(16, 16, 1), blk, GEMM_SMEM_BYTES>>>(
            gx, wq, gq, nullptr, M, DM, DM, DM, DM, DM);
        gemm_tf32<0, 0><<<dim3(16, 16, 1), blk, GEMM_SMEM_BYTES>>>(
            gx, wk, gk, nullptr, M, DM, DM, DM, DM, DM);
        gemm_tf32<0, 0><<<dim3(16, 16, 1), blk, GEMM_SMEM_BYTES>>>(
            gx, wv, gv, nullptr, M, DM, DM, DM, DM, DM);

        // fused scores + softmax -> p (written once)
        attn_scores_softmax<<<dim3(SQ / 32, BB * NH), dim3(512), SC_SMEM_BYTES>>>(
            gq, gk, attn_bias, mask, p);

        // o = p @ v   (batched over b,h)
        gemm_tf32<0, 1><<<dim3(1, SQ / 128, BB * NH), blk, GEMM_SMEM_BYTES>>>(
            p, gv, gt, nullptr, SQ, DK, SQ, SQ, DM, DM);

        // x = LN(o + x)
        resid_ln<<<M, blk>>>(gt, gx, ln1_g + (long)n * DM, ln1_b + (long)n * DM, gx);

        // h = gelu(x W1 + b1)
        gemm_tf32<2, 0><<<dim3(32, 16, 1), blk, GEMM_SMEM_BYTES>>>(
            gx, W1 + (long)n * DM * DFF, gh, b1 + (long)n * DFF, M, DFF, DM, DM, DFF, DFF);
        // f = h W2 + b2
        gemm_tf32<1, 0><<<dim3(16, 16, 1), blk, GEMM_SMEM_BYTES>>>(
            gh, W2 + (long)n * DFF * DM, gt, b2 + (long)n * DM, M, DM, DFF, DFF, DM, DM);
        // x = LN(x + f)
        resid_ln<<<M, blk>>>(gx, gt, ln2_g + (long)n * DM, ln2_b + (long)n * DM, gx);
    }

    cudaMemcpyAsync(outx, gx, sizeof(float) * BB * SQ * DM, cudaMemcpyDeviceToDevice);
}

// round 9
// speedup vs baseline: 3.1088x; 1.1217x over previous
#include <cuda_runtime.h>
#include <cuda_bf16.h>
#include <math.h>

// Problem constants
#define BB   2
#define SQ   1024
#define DM   1024
#define NH   16
#define DK   64
#define DFF  2048
#define NL   4

// ---------------------------------------------------------------------------
// Scratch (device globals — no allocation allowed)
// ---------------------------------------------------------------------------
__device__ __align__(16) float g_q[BB * SQ * DM];
__device__ __align__(16) float g_k[BB * SQ * DM];
__device__ __align__(16) float g_v[BB * SQ * DM];
__device__ __align__(16) float g_x[BB * SQ * DM];
__device__ __align__(16) float g_t[BB * SQ * DM];
__device__ __align__(16) float g_h[BB * SQ * DFF];
// tf32-pre-rounded weights
__device__ __align__(16) float g_wq[NL * DM * DM];
__device__ __align__(16) float g_wk[NL * DM * DM];
__device__ __align__(16) float g_wv[NL * DM * DM];
__device__ __align__(16) float g_w1[NL * DM * DFF];
__device__ __align__(16) float g_w2[NL * DFF * DM];

// ---------------------------------------------------------------------------
// Helpers
// ---------------------------------------------------------------------------
__device__ __forceinline__ unsigned f2tf(float f) {
    unsigned u;
    asm("cvt.rna.tf32.f32 %0, %1;" : "=r"(u) : "f"(f));
    return u;
}
__device__ __forceinline__ float f2tf_f(float f) {
    return __uint_as_float(f2tf(f));
}

__device__ __forceinline__ void mma8(float* c, const unsigned* a, const unsigned* b) {
    asm volatile(
        "mma.sync.aligned.m16n8k8.row.col.f32.tf32.tf32.f32 "
        "{%0,%1,%2,%3},{%4,%5,%6,%7},{%8,%9},{%0,%1,%2,%3};\n"
        : "+f"(c[0]), "+f"(c[1]), "+f"(c[2]), "+f"(c[3])
        : "r"(a[0]), "r"(a[1]), "r"(a[2]), "r"(a[3]), "r"(b[0]), "r"(b[1]));
}

__device__ __forceinline__ void cpa16(float* smem_dst, const float* gsrc) {
    unsigned s = (unsigned)__cvta_generic_to_shared(smem_dst);
    asm volatile("cp.async.cg.shared.global [%0], [%1], 16;" :: "r"(s), "l"(gsrc));
}
__device__ __forceinline__ void cpa_commit() {
    asm volatile("cp.async.commit_group;" ::: "memory");
}
__device__ __forceinline__ void cpa_wait1() {
    asm volatile("cp.async.wait_group 1;" ::: "memory");
}
__device__ __forceinline__ void cpa_wait0() {
    asm volatile("cp.async.wait_group 0;" ::: "memory");
}

__device__ __forceinline__ float gelu_tanh_f(float x) {
    float x3 = x * x * x;
    return 0.5f * x * (1.0f + tanhf(0.7978845608028654f * (x + 0.044715f * x3)));
}

__device__ __forceinline__ float block_sum256(float v, float* sh) {
    #pragma unroll
    for (int o = 16; o; o >>= 1) v += __shfl_xor_sync(0xffffffffu, v, o);
    int w = threadIdx.x >> 5;
    if ((threadIdx.x & 31) == 0) sh[w] = v;
    __syncthreads();
    float r = (threadIdx.x < 8) ? sh[threadIdx.x] : 0.0f;
    if (threadIdx.x < 32) {
        #pragma unroll
        for (int o = 4; o; o >>= 1) r += __shfl_xor_sync(0xffffffffu, r, o);
        if (threadIdx.x == 0) sh[0] = r;
    }
    __syncthreads();
    r = sh[0];
    __syncthreads();
    return r;
}

// ---------------------------------------------------------------------------
// Weight pre-rounding: dst[i] = tf32_rna(src[i])  (float4 grid-stride)
// ---------------------------------------------------------------------------
__global__ void __launch_bounds__(256) round_w(
    const float4* __restrict__ src, float4* __restrict__ dst, int n4)
{
    for (int i = blockIdx.x * blockDim.x + threadIdx.x; i < n4;
         i += gridDim.x * blockDim.x) {
        float4 v = src[i];
        v.x = f2tf_f(v.x); v.y = f2tf_f(v.y);
        v.z = f2tf_f(v.z); v.w = f2tf_f(v.w);
        dst[i] = v;
    }
}

// ---------------------------------------------------------------------------
// tf32 tensor-core GEMM body, cp.async 2-stage pipeline.
// C[M,N] = A[M,K] * B[K,N] (+bias)(+gelu)(+round-to-tf32 on store)
// 128x64 tile, BK=32, 256 threads = 8 warps (4x2), warp tile 32x32.
// CA: 1 = cvt.rna A fragments (A source is full-precision fp32),
//     0 = raw bits (A source already tf32-rounded).
// B fragments are ALWAYS raw bits — B must be pre-rounded (weights/v/h).
// EPI: 0 none, 1 +bias, 2 +bias+gelu.  RND: round C to tf32 on store.
// ---------------------------------------------------------------------------
#define GEMM_SMEM_BYTES ((2 * 128 * 36 + 2 * 32 * 72) * 4)

template<int EPI, int CA, int RND>
__device__ __forceinline__ void gemm_body(
    const float* __restrict__ A, const float* __restrict__ Bm,
    float* __restrict__ C, const float* __restrict__ bias,
    int M, int N, int K, int lda, int ldb, int ldc, float* dsm)
{
    float* As = dsm;                 // [2][128][36]
    float* Bs = dsm + 2 * 128 * 36;  // [2][32][72]

    int t = threadIdx.x;
    int lane = t & 31, w = t >> 5;
    int wm = w >> 1, wn = w & 1;
    int lq = lane >> 2, lr = lane & 3;
    int row0 = blockIdx.y * 128, col0 = blockIdx.x * 64;

    float acc[2][4][4];
    #pragma unroll
    for (int i = 0; i < 2; i++)
        #pragma unroll
        for (int j = 0; j < 4; j++)
            #pragma unroll
            for (int l = 0; l < 4; l++) acc[i][j][l] = 0.0f;

    int a_row = t >> 3;             // 0..31 (x4 -> 128)
    int a_kc  = (t & 7) * 4;
    int b_kr  = t >> 4;             // 0..15 (x2 -> 32)
    int b_nc  = (t & 15) * 4;

    #define LOAD_TILES(s, k0)                                                   \
        {                                                                       \
            _Pragma("unroll")                                                   \
            for (int i = 0; i < 4; i++) {                                       \
                int row = a_row + i * 32;                                       \
                cpa16(&As[(s) * 4608 + row * 36 + a_kc],                        \
                      &A[(long)(row0 + row) * lda + (k0) + a_kc]);              \
            }                                                                   \
            _Pragma("unroll")                                                   \
            for (int i = 0; i < 2; i++) {                                       \
                int kr = b_kr + i * 16;                                         \
                cpa16(&Bs[(s) * 2304 + kr * 72 + b_nc],                         \
                      &Bm[(long)((k0) + kr) * ldb + col0 + b_nc]);              \
            }                                                                   \
        }

    LOAD_TILES(0, 0);
    cpa_commit();

    int KT = K >> 5;
    for (int kt = 0; kt < KT; kt++) {
        int cur = kt & 1;
        if (kt + 1 < KT) {
            LOAD_TILES(cur ^ 1, (kt + 1) * 32);
            cpa_commit();
            cpa_wait1();
        } else {
            cpa_wait0();
        }
        __syncthreads();

        const float* Ac = &As[cur * 4608];
        const float* Bc = &Bs[cur * 2304];
        #pragma unroll
        for (int ks = 0; ks < 4; ks++) {
            int kb = ks * 8;
            unsigned a[2][4], bf[4][2];
            #pragma unroll
            for (int mi = 0; mi < 2; mi++) {
                int ar = wm * 32 + mi * 16 + lq;
                if (CA) {
                    a[mi][0] = f2tf(Ac[ar * 36 + kb + lr]);
                    a[mi][1] = f2tf(Ac[(ar + 8) * 36 + kb + lr]);
                    a[mi][2] = f2tf(Ac[ar * 36 + kb + 4 + lr]);
                    a[mi][3] = f2tf(Ac[(ar + 8) * 36 + kb + 4 + lr]);
                } else {
                    a[mi][0] = __float_as_uint(Ac[ar * 36 + kb + lr]);
                    a[mi][1] = __float_as_uint(Ac[(ar + 8) * 36 + kb + lr]);
                    a[mi][2] = __float_as_uint(Ac[ar * 36 + kb + 4 + lr]);
                    a[mi][3] = __float_as_uint(Ac[(ar + 8) * 36 + kb + 4 + lr]);
                }
            }
            #pragma unroll
            for (int nj = 0; nj < 4; nj++) {
                int bn = wn * 32 + nj * 8 + lq;
                bf[nj][0] = __float_as_uint(Bc[(kb + lr) * 72 + bn]);
                bf[nj][1] = __float_as_uint(Bc[(kb + 4 + lr) * 72 + bn]);
            }
            #pragma unroll
            for (int mi = 0; mi < 2; mi++)
                #pragma unroll
                for (int nj = 0; nj < 4; nj++)
                    mma8(acc[mi][nj], a[mi], bf[nj]);
        }
        __syncthreads();
    }
    #undef LOAD_TILES

    #pragma unroll
    for (int mi = 0; mi < 2; mi++) {
        #pragma unroll
        for (int nj = 0; nj < 4; nj++) {
            int r = row0 + wm * 32 + mi * 16 + lq;
            int c = col0 + wn * 32 + nj * 8 + 2 * lr;
            float v0 = acc[mi][nj][0], v1 = acc[mi][nj][1];
            float v2 = acc[mi][nj][2], v3 = acc[mi][nj][3];
            if (EPI >= 1) {
                float b0 = bias[c], b1 = bias[c + 1];
                v0 += b0; v1 += b1; v2 += b0; v3 += b1;
            }
            if (EPI == 2) {
                v0 = gelu_tanh_f(v0); v1 = gelu_tanh_f(v1);
                v2 = gelu_tanh_f(v2); v3 = gelu_tanh_f(v3);
            }
            if (RND) {
                v0 = f2tf_f(v0); v1 = f2tf_f(v1);
                v2 = f2tf_f(v2); v3 = f2tf_f(v3);
            }
            *(float2*)&C[(long)r * ldc + c] = make_float2(v0, v1);
            *(float2*)&C[(long)(r + 8) * ldc + c] = make_float2(v2, v3);
        }
    }
}

template<int EPI, int CA, int RND, int ATTN>
__global__ void __launch_bounds__(256) gemm_tf32(
    const float* __restrict__ A, const float* __restrict__ Bm,
    float* __restrict__ C, const float* __restrict__ bias,
    int M, int N, int K, int lda, int ldb, int ldc)
{
    if (ATTN) {
        int z = blockIdx.z;
        int b = z >> 4;
        int h = z & 15;
        A  += (long)z * SQ * SQ;
        Bm += (long)b * SQ * DM + h * DK;
        C  += (long)b * SQ * DM + h * DK;
    }
    extern __shared__ float dsm[];
    gemm_body<EPI, CA, RND>(A, Bm, C, bias, M, N, K, lda, ldb, ldc, dsm);
}

// Merged QKV: blockIdx.z selects which projection. Outputs rounded to tf32
// (q,k,v only feed MMAs downstream).
__global__ void __launch_bounds__(256) gemm_qkv(
    const float* __restrict__ A,
    const float* __restrict__ B0, const float* __restrict__ B1,
    const float* __restrict__ B2,
    float* __restrict__ C0, float* __restrict__ C1, float* __restrict__ C2)
{
    extern __shared__ float dsm[];
    int zz = blockIdx.z;
    const float* Bm = (zz == 0) ? B0 : (zz == 1) ? B1 : B2;
    float* C = (zz == 0) ? C0 : (zz == 1) ? C1 : C2;
    gemm_body<0, 1, 1>(A, Bm, C, nullptr, BB * SQ, DM, DM, DM, DM, DM, dsm);
}

// ---------------------------------------------------------------------------
// Fused scores + softmax, v3: register-resident score strip.
// Block = (z, 16 q-rows) x 1024 keys. 256 threads = 8 warps.
// Warp w owns key columns [w*16, w*16+16) of each 128-key slab.
// q,k are ALREADY tf32-rounded (QKV epilogue) -> raw-bit fragments are exact.
// grid: (SQ/16, B*NH). 2 CTAs/SM (79KB smem).
// ---------------------------------------------------------------------------
#define SC3_SMEM_BYTES ((16 * 68 + 2 * 128 * 68 + 128 + 128 + 1024) * 4)

__global__ void __launch_bounds__(256, 2) attn_scores_softmax(
    const float* __restrict__ q, const float* __restrict__ k,
    const float* __restrict__ bias, const int* __restrict__ mask,
    float* __restrict__ p)
{
    extern __shared__ char smx[];
    unsigned* Qs = (unsigned*)smx;               // [16][68] tf32 bits
    float* Ks   = (float*)(Qs + 16 * 68);        // [2][128][68] tf32-valued
    float* rmax = Ks + 2 * 128 * 68;             // [16][8]
    float* rsum = rmax + 128;                    // [16][8]
    int*   msk  = (int*)(rsum + 128);            // [1024]

    int t = threadIdx.x;
    int lane = t & 31, w = t >> 5;               // 8 warps
    int lq = lane >> 2, lr = lane & 3;
    int z = blockIdx.y, b = z >> 4, h = z & 15;
    int q0 = blockIdx.x * 16;

    const float* qb = q + (long)b * SQ * DM + h * DK;
    const float* kb = k + (long)b * SQ * DM + h * DK;
    const float* bz = bias + (long)z * SQ * SQ;

    // K slab loader: 128 rows x 64 floats = 2048 float4, 256 thr x 8
    int k_row = t >> 4;             // 0..15 (x8 -> 128)
    int k_kc  = (t & 15) * 4;
    #define LOAD_SLAB(s, key0)                                                  \
        {                                                                       \
            _Pragma("unroll")                                                   \
            for (int i = 0; i < 8; i++) {                                       \
                int row = k_row + i * 16;                                       \
                cpa16(&Ks[(s) * 8704 + row * 68 + k_kc],                        \
                      &kb[(long)((key0) + row) * DM + k_kc]);                   \
            }                                                                   \
        }

    LOAD_SLAB(0, 0);
    cpa_commit();

    // Q tile 16x64 -> smem (already tf32-rounded; store raw bits)
    {
        int row = t >> 4;
        int kc = (t & 15) * 4;
        float4 v = *(const float4*)&qb[(long)(q0 + row) * DM + kc];
        unsigned* dst = &Qs[row * 68 + kc];
        dst[0] = __float_as_uint(v.x); dst[1] = __float_as_uint(v.y);
        dst[2] = __float_as_uint(v.z); dst[3] = __float_as_uint(v.w);
    }
    ((int4*)msk)[t] = ((const int4*)(mask + b * SQ))[t];

    float sc[8][8];                  // [slab][frag] register scores
    float m0 = -3.4e38f, m1 = -3.4e38f;   // running row maxes (rows lq, lq+8)

    const int c0b = w * 16 + 2 * lr;       // nj=0 col within slab
    long row_a = (long)(q0 + lq) * SQ;
    long row_b = (long)(q0 + lq + 8) * SQ;

    #pragma unroll
    for (int slab = 0; slab < 8; slab++) {
        int cur = slab & 1;
        int key0 = slab * 128;
        if (slab + 1 < 8) {
            LOAD_SLAB(cur ^ 1, key0 + 128);
            cpa_commit();
        }
        // prefetch bias for this slab (overlaps with wait+mma)
        int c0 = key0 + c0b;
        int c1 = c0 + 8;
        float2 B00 = *(const float2*)&bz[row_a + c0];
        float2 B01 = *(const float2*)&bz[row_a + c1];
        float2 B10 = *(const float2*)&bz[row_b + c0];
        float2 B11 = *(const float2*)&bz[row_b + c1];
        if (slab + 1 < 8) cpa_wait1(); else cpa_wait0();
        __syncthreads();

        #pragma unroll
        for (int j = 0; j < 8; j++) sc[slab][j] = 0.0f;

        const float* Kc = &Ks[cur * 8704];
        #pragma unroll
        for (int ks = 0; ks < 8; ks++) {
            int kv = ks * 8;
            unsigned a[4], bf0[2], bf1[2];
            a[0] = Qs[lq * 68 + kv + lr];
            a[1] = Qs[(lq + 8) * 68 + kv + lr];
            a[2] = Qs[lq * 68 + kv + 4 + lr];
            a[3] = Qs[(lq + 8) * 68 + kv + 4 + lr];
            int kn0 = w * 16 + lq;
            bf0[0] = __float_as_uint(Kc[kn0 * 68 + kv + lr]);
            bf0[1] = __float_as_uint(Kc[kn0 * 68 + kv + 4 + lr]);
            bf1[0] = __float_as_uint(Kc[(kn0 + 8) * 68 + kv + lr]);
            bf1[1] = __float_as_uint(Kc[(kn0 + 8) * 68 + kv + 4 + lr]);
            mma8(&sc[slab][0], a, bf0);
            mma8(&sc[slab][4], a, bf1);
        }

        // fold scale + bias + mask; track row maxes
        int mk0a = msk[c0], mk0b = msk[c0 + 1];
        int mk1a = msk[c1], mk1b = msk[c1 + 1];
        float v0 = sc[slab][0] * 0.125f + B00.x; if (mk0a == 0) v0 = -9e15f;
        float v1 = sc[slab][1] * 0.125f + B00.y; if (mk0b == 0) v1 = -9e15f;
        float v2 = sc[slab][2] * 0.125f + B10.x; if (mk0a == 0) v2 = -9e15f;
        float v3 = sc[slab][3] * 0.125f + B10.y; if (mk0b == 0) v3 = -9e15f;
        float v4 = sc[slab][4] * 0.125f + B01.x; if (mk1a == 0) v4 = -9e15f;
        float v5 = sc[slab][5] * 0.125f + B01.y; if (mk1b == 0) v5 = -9e15f;
        float v6 = sc[slab][6] * 0.125f + B11.x; if (mk1a == 0) v6 = -9e15f;
        float v7 = sc[slab][7] * 0.125f + B11.y; if (mk1b == 0) v7 = -9e15f;
        sc[slab][0] = v0; sc[slab][1] = v1; sc[slab][2] = v2; sc[slab][3] = v3;
        sc[slab][4] = v4; sc[slab][5] = v5; sc[slab][6] = v6; sc[slab][7] = v7;
        m0 = fmaxf(m0, fmaxf(fmaxf(v0, v1), fmaxf(v4, v5)));
        m1 = fmaxf(m1, fmaxf(fmaxf(v2, v3), fmaxf(v6, v7)));
        __syncthreads();
    }
    #undef LOAD_SLAB

    // -- row max: quad reduce (over lr), then cross-warp via smem --
    m0 = fmaxf(m0, __shfl_xor_sync(0xffffffffu, m0, 1));
    m0 = fmaxf(m0, __shfl_xor_sync(0xffffffffu, m0, 2));
    m1 = fmaxf(m1, __shfl_xor_sync(0xffffffffu, m1, 1));
    m1 = fmaxf(m1, __shfl_xor_sync(0xffffffffu, m1, 2));
    if (lr == 0) {
        rmax[lq * 8 + w] = m0;
        rmax[(lq + 8) * 8 + w] = m1;
    }
    __syncthreads();
    float rm0 = rmax[lq * 8];
    float rm1 = rmax[(lq + 8) * 8];
    #pragma unroll
    for (int j = 1; j < 8; j++) {
        rm0 = fmaxf(rm0, rmax[lq * 8 + j]);
        rm1 = fmaxf(rm1, rmax[(lq + 8) * 8 + j]);
    }

    // -- exp + row sum --
    float s0 = 0.0f, s1 = 0.0f;
    #pragma unroll
    for (int slab = 0; slab < 8; slab++) {
        float e0 = __expf(sc[slab][0] - rm0);
        float e1 = __expf(sc[slab][1] - rm0);
        float e4 = __expf(sc[slab][4] - rm0);
        float e5 = __expf(sc[slab][5] - rm0);
        float e2 = __expf(sc[slab][2] - rm1);
        float e3 = __expf(sc[slab][3] - rm1);
        float e6 = __expf(sc[slab][6] - rm1);
        float e7 = __expf(sc[slab][7] - rm1);
        s0 += (e0 + e1) + (e4 + e5);
        s1 += (e2 + e3) + (e6 + e7);
        sc[slab][0] = e0; sc[slab][1] = e1; sc[slab][2] = e2; sc[slab][3] = e3;
        sc[slab][4] = e4; sc[slab][5] = e5; sc[slab][6] = e6; sc[slab][7] = e7;
    }
    s0 += __shfl_xor_sync(0xffffffffu, s0, 1);
    s0 += __shfl_xor_sync(0xffffffffu, s0, 2);
    s1 += __shfl_xor_sync(0xffffffffu, s1, 1);
    s1 += __shfl_xor_sync(0xffffffffu, s1, 2);
    if (lr == 0) {
        rsum[lq * 8 + w] = s0;
        rsum[(lq + 8) * 8 + w] = s1;
    }
    __syncthreads();
    float t0 = 0.0f, t1 = 0.0f;
    #pragma unroll
    for (int j = 0; j < 8; j++) {
        t0 += rsum[lq * 8 + j];
        t1 += rsum[(lq + 8) * 8 + j];
    }
    float inv0 = 1.0f / t0;
    float inv1 = 1.0f / t1;

    // -- write p --
    float* pr0 = p + (long)z * SQ * SQ + row_a;
    float* pr1 = p + (long)z * SQ * SQ + row_b;
    #pragma unroll
    for (int slab = 0; slab < 8; slab++) {
        int c0 = slab * 128 + c0b;
        int c1 = c0 + 8;
        *(float2*)&pr0[c0] = make_float2(sc[slab][0] * inv0, sc[slab][1] * inv0);
        *(float2*)&pr0[c1] = make_float2(sc[slab][4] * inv0, sc[slab][5] * inv0);
        *(float2*)&pr1[c0] = make_float2(sc[slab][2] * inv1, sc[slab][3] * inv1);
        *(float2*)&pr1[c1] = make_float2(sc[slab][6] * inv1, sc[slab][7] * inv1);
    }
}

// ---------------------------------------------------------------------------
// out = LayerNorm(A + Bx) * g + b   (row length 1024, one block per row)
// ---------------------------------------------------------------------------
__global__ void __launch_bounds__(256) resid_ln(
    const float* __restrict__ A, const float* __restrict__ Bx,
    const float* __restrict__ gw, const float* __restrict__ bw,
    float* __restrict__ out)
{
    __shared__ float sh[8];
    long base = (long)blockIdx.x * DM;
    int t = threadIdx.x;
    float4 a = *(const float4*)&A[base + t * 4];
    float4 b = *(const float4*)&Bx[base + t * 4];
    float4 v = make_float4(a.x + b.x, a.y + b.y, a.z + b.z, a.w + b.w);

    float s = block_sum256(v.x + v.y + v.z + v.w, sh);
    float mu = s * (1.0f / DM);
    float dx = v.x - mu, dy = v.y - mu, dz = v.z - mu, dw = v.w - mu;
    float ss = block_sum256(dx * dx + dy * dy + dz * dz + dw * dw, sh);
    float rstd = rsqrtf(ss * (1.0f / DM) + 1e-6f);

    float4 g4 = *(const float4*)&gw[t * 4];
    float4 b4 = *(const float4*)&bw[t * 4];
    float4 o;
    o.x = dx * rstd * g4.x + b4.x;
    o.y = dy * rstd * g4.y + b4.y;
    o.z = dz * rstd * g4.z + b4.z;
    o.w = dw * rstd * g4.w + b4.w;
    *(float4*)&out[base + t * 4] = o;
}

// ---------------------------------------------------------------------------
// Launch
// ---------------------------------------------------------------------------
extern "C" void kernel_launch(void* const* d_in, const int* in_sizes, int n_in,
                              void* d_out, int out_size)
{
    const float* x_in      = (const float*)d_in[0];
    const int*   mask      = (const int*)  d_in[1];
    const float* attn_bias = (const float*)d_in[2];
    const float* Wq        = (const float*)d_in[3];
    const float* Wk        = (const float*)d_in[4];
    const float* Wv        = (const float*)d_in[5];
    const float* ln1_g     = (const float*)d_in[6];
    const float* ln1_b     = (const float*)d_in[7];
    const float* W1        = (const float*)d_in[8];
    const float* b1        = (const float*)d_in[9];
    const float* W2        = (const float*)d_in[10];
    const float* b2        = (const float*)d_in[11];
    const float* ln2_g     = (const float*)d_in[12];
    const float* ln2_b     = (const float*)d_in[13];

    float* out  = (float*)d_out;
    float* outx = out + (long)NL * BB * NH * SQ * SQ;

    float *gq, *gk, *gv, *gx, *gt, *gh;
    float *wqr, *wkr, *wvr, *w1r, *w2r;
    cudaGetSymbolAddress((void**)&gq, g_q);
    cudaGetSymbolAddress((void**)&gk, g_k);
    cudaGetSymbolAddress((void**)&gv, g_v);
    cudaGetSymbolAddress((void**)&gx, g_x);
    cudaGetSymbolAddress((void**)&gt, g_t);
    cudaGetSymbolAddress((void**)&gh, g_h);
    cudaGetSymbolAddress((void**)&wqr, g_wq);
    cudaGetSymbolAddress((void**)&wkr, g_wk);
    cudaGetSymbolAddress((void**)&wvr, g_wv);
    cudaGetSymbolAddress((void**)&w1r, g_w1);
    cudaGetSymbolAddress((void**)&w2r, g_w2);

    static int smem_set = 0;
    if (!smem_set) {
        cudaFuncSetAttribute(attn_scores_softmax,
                             cudaFuncAttributeMaxDynamicSharedMemorySize, SC3_SMEM_BYTES);
        cudaFuncSetAttribute(gemm_qkv,
                             cudaFuncAttributeMaxDynamicSharedMemorySize, GEMM_SMEM_BYTES);
        cudaFuncSetAttribute(gemm_tf32<0, 1, 0, 1>,
                             cudaFuncAttributeMaxDynamicSharedMemorySize, GEMM_SMEM_BYTES);
        cudaFuncSetAttribute(gemm_tf32<2, 1, 1, 0>,
                             cudaFuncAttributeMaxDynamicSharedMemorySize, GEMM_SMEM_BYTES);
        cudaFuncSetAttribute(gemm_tf32<1, 0, 0, 0>,
                             cudaFuncAttributeMaxDynamicSharedMemorySize, GEMM_SMEM_BYTES);
        smem_set = 1;
    }

    // Pre-round all weights to tf32 (once per launch; inside graph, deterministic)
    round_w<<<2048, 256>>>((const float4*)Wq, (float4*)wqr, NL * DM * DM / 4);
    round_w<<<2048, 256>>>((const float4*)Wk, (float4*)wkr, NL * DM * DM / 4);
    round_w<<<2048, 256>>>((const float4*)Wv, (float4*)wvr, NL * DM * DM / 4);
    round_w<<<2048, 256>>>((const float4*)W1, (float4*)w1r, NL * DM * DFF / 4);
    round_w<<<2048, 256>>>((const float4*)W2, (float4*)w2r, NL * DFF * DM / 4);

    cudaMemcpyAsync(gx, x_in, sizeof(float) * BB * SQ * DM, cudaMemcpyDeviceToDevice);

    dim3 blk(256);
    const int M = BB * SQ;  // 2048

    for (int n = 0; n < NL; n++) {
        float* p = out + (long)n * BB * NH * SQ * SQ;

        // QKV projections, one merged launch; outputs tf32-rounded
        gemm_qkv<<<dim3(16, 16, 3), blk, GEMM_SMEM_BYTES>>>(
            gx, wqr + (long)n * DM * DM, wkr + (long)n * DM * DM,
            wvr + (long)n * DM * DM, gq, gk, gv);

        // fused scores + softmax -> p (written once)
        attn_scores_softmax<<<dim3(SQ / 16, BB * NH), blk, SC3_SMEM_BYTES>>>(
            gq, gk, attn_bias, mask, p);

        // o = p @ v  (A=p full precision -> CA=1; B=v pre-rounded)
        gemm_tf32<0, 1, 0, 1><<<dim3(1, SQ / 128, BB * NH), blk, GEMM_SMEM_BYTES>>>(
            p, gv, gt, nullptr, SQ, DK, SQ, SQ, DM, DM);

        // x = LN(o + x)
        resid_ln<<<M, blk>>>(gt, gx, ln1_g + (long)n * DM, ln1_b + (long)n * DM, gx);

        // h = gelu(x W1 + b1); h rounded to tf32 (only feeds FFN2 MMA)
        gemm_tf32<2, 1, 1, 0><<<dim3(32, 16, 1), blk, GEMM_SMEM_BYTES>>>(
            gx, w1r + (long)n * DM * DFF, gh, b1 + (long)n * DFF,
            M, DFF, DM, DM, DFF, DFF);
        // f = h W2 + b2  (A=h pre-rounded -> CA=0)
        gemm_tf32<1, 0, 0, 0><<<dim3(16, 16, 1), blk, GEMM_SMEM_BYTES>>>(
            gh, w2r + (long)n * DFF * DM, gt, b2 + (long)n * DM,
            M, DM, DFF, DFF, DM, DM);
        // x = LN(x + f)
        resid_ln<<<M, blk>>>(gx, gt, ln2_g + (long)n * DM, ln2_b + (long)n * DM, gx);
    }

    cudaMemcpyAsync(outx, gx, sizeof(float) * BB * SQ * DM, cudaMemcpyDeviceToDevice);
}